// round 1
// baseline (speedup 1.0000x reference)
#include <cuda_runtime.h>

#define TN 32768
#define TLOOP 32799
#define NCHUNK 2050
#define NSTEPS (NCHUNK*16)   /* 32800 */
#define NBC 14
#define NACL 10
#define NACG 35
#define KACN 52
#define K0 20
#define K1 32
#define PADL 50              /* (K0-1)+(K1-1) */
#define XPLEN (TN + PADL)    /* 32818 */
#define RELSTRIDE 32832

__device__ float g_xp[XPLEN];
__device__ float g_drive[NSTEPS*NBC];
__device__ float g_rel[2*NBC*RELSTRIDE];
__device__ float g_kbc[NBC*K0];
__device__ float g_kglu[K1];

__device__ __forceinline__ float fsig(float z){
    return __fdividef(1.0f, 1.0f + __expf(-z));
}

// double-exponential AC kernel -> IIR coefficients (exact FIR-equivalent with
// truncation correction):
//   kern(L) = A*r1^L - B*r2^L  (L=0 newest), normalized by L2 norm over 52 taps
__device__ __forceinline__ void ac_coef(float ltr, float ltd,
    float &A, float &B, float &r1, float &r2, float &c1, float &c2){
    float tr = expf(ltr), td = expf(ltd);
    float beta = (td + tr) / (td * tr);
    float n2 = 0.f;
    for (int k = 0; k < KACN; k++){
        float t = 0.8f - (float)k * (1.0f/64.0f);
        float v = expf(-t/td) - expf(-beta*t);
        n2 = fmaf(v, v, n2);
    }
    float inv = 1.0f / sqrtf(n2);
    const float c0 = 0.8f - 51.0f*(1.0f/64.0f);
    A  = expf(-c0/td) * inv;
    B  = expf(-beta*c0) * inv;
    r1 = expf(-1.0f/(64.0f*td));
    r2 = expf(-beta*(1.0f/64.0f));
    c1 = expf(-0.8125f/td);        /* r1^52 */
    c2 = expf(-beta*0.8125f);      /* r2^52 */
}

// ---------------- setup: BC biphasic kernels + iGluSnFR kernel ----------------
__global__ void setup_kernel(const float* __restrict__ lks){
    int t = threadIdx.x;
    if (t < NBC){
        float speed = expf(lks[t]);
        float ct = (t < 5) ? -1.0f : 1.0f;
        float vals[K0]; float n2 = 0.f;
        #pragma unroll
        for (int j = 0; j < K0; j++){
            float ts = (float)j * (1.0f/64.0f) * speed;
            float a = ts / 0.05f, b = ts / 0.1f;
            float v = a*a*expf(-a) - 0.8f*b*b*expf(-b);
            v *= ct;
            vals[j] = v; n2 += v*v;
        }
        float inv = 1.0f / sqrtf(n2);
        #pragma unroll
        for (int j = 0; j < K0; j++) g_kbc[t*K0+j] = vals[j]*inv;
    }
    if (t == 32){
        float vals[K1]; float s = 0.f;
        #pragma unroll
        for (int j = 0; j < K1; j++){
            float tg = (float)j * (1.0f/64.0f);
            float v = (1.0f - expf(-tg/0.02f)) * expf(-tg/0.1f);
            vals[j] = v; s += v;
        }
        #pragma unroll
        for (int j = 0; j < K1; j++) g_kglu[j] = vals[j]/s;
    }
}

// ---------------- stimulus affine + edge padding ----------------
__global__ void xp_kernel(const float* __restrict__ x,
                          const float* __restrict__ sb,
                          const float* __restrict__ ss){
    int i = blockIdx.x*blockDim.x + threadIdx.x;
    if (i >= XPLEN) return;
    float es = expf(ss[0]); float b = sb[0];
    int s = i - PADL; if (s < 0) s = 0;
    g_xp[i] = x[s]*es + b;
}

// ---------------- per-BC 20-tap FIR -> drive[NSTEPS][NBC] ----------------
__global__ void drive_kernel(){
    __shared__ float skb[NBC*K0];
    int tid = threadIdx.x;
    for (int i = tid; i < NBC*K0; i += blockDim.x) skb[i] = g_kbc[i];
    __syncthreads();
    int n = blockIdx.x*blockDim.x + tid;
    if (n >= NSTEPS) return;
    if (n >= TLOOP){
        #pragma unroll
        for (int c = 0; c < NBC; c++) g_drive[n*NBC+c] = 0.f;
        return;
    }
    float xw[K0];
    #pragma unroll
    for (int j = 0; j < K0; j++) xw[j] = g_xp[n + j];
    #pragma unroll
    for (int c = 0; c < NBC; c++){
        float a0 = 0.f, a1 = 0.f;
        #pragma unroll
        for (int j = 0; j < K0; j++){
            float w = skb[c*K0+j];
            float v = xw[K0-1-j];       /* drive[n][c] = sum_j k[j]*xp[n+19-j] */
            if (j & 1) a1 = fmaf(w, v, a1); else a0 = fmaf(w, v, a0);
        }
        g_drive[n*NBC+c] = a0 + a1;
    }
}

// ---------------- the sequential scan: 2 blocks (pathways) x 1 warp ----------------
__global__ void __launch_bounds__(32,1) scan_kernel(
    const float* __restrict__ P_sigoff, const float* __restrict__ P_lslope,
    const float* __restrict__ P_lp01,  const float* __restrict__ P_lp12,
    const float* __restrict__ P_lipc,  const float* __restrict__ P_lrrpc,
    const float* __restrict__ P_ipst,  const float* __restrict__ P_rrpst,
    const float* __restrict__ P_laclbc, const float* __restrict__ P_lbcacl,
    const float* __restrict__ P_acltr, const float* __restrict__ P_acltd,
    const float* __restrict__ P_aclsl, const float* __restrict__ P_aclof,
    const float* __restrict__ P_lacgbc, const float* __restrict__ P_lbcacg,
    const float* __restrict__ P_acgtr, const float* __restrict__ P_acgtd,
    const float* __restrict__ P_acgsl, const float* __restrict__ P_acgof,
    const float* __restrict__ P_laclacg, const float* __restrict__ P_bcnoff)
{
    const int path = blockIdx.x;
    const int l = threadIdx.x;
    __shared__ float ringA[NACL*53];
    __shared__ float ringG[NACG*53];
    __shared__ float dbuf[2][16*NBC];
    for (int i = l; i < NACL*53; i += 32) ringA[i] = 0.f;
    for (int i = l; i < NACG*53; i += 32) ringG[i] = 0.f;

    // ---- BC role (lane < 14) ----
    float c_off=0.f, c_slope=0.f, c_p01=0.f, c_p12=0.f, c_ipcap=0.f, c_irrp=0.f;
    float ip=0.f, rrp=0.f;
    float wfbA[NACL], wfbG[NACG];
    #pragma unroll
    for (int j = 0; j < NACL; j++) wfbA[j] = 0.f;
    #pragma unroll
    for (int j = 0; j < NACG; j++) wfbG[j] = 0.f;
    if (l < NBC){
        c_off   = P_sigoff[l] + (path ? P_bcnoff[l] : 0.f);
        c_slope = expf(P_lslope[l]);
        c_p01   = expf(P_lp01[l]);
        c_p12   = expf(P_lp12[l]);
        c_ipcap = expf(P_lipc[l]);
        float rc = expf(P_lrrpc[l]);
        c_irrp = 1.0f / rc;
        ip  = c_ipcap / (1.0f + expf(-P_ipst[l]));
        rrp = rc      / (1.0f + expf(-P_rrpst[l]));
        #pragma unroll
        for (int j = 0; j < NACL; j++) wfbA[j] = -expf(P_laclbc[l*NACL+j]);
        if (path){
            #pragma unroll
            for (int j = 0; j < NACG; j++) wfbG[j] = -expf(P_lacgbc[l*NACG+j]);
        }
    }

    // ---- ACL role (lane < 10) ----
    float aA=0.f,aB=0.f,aR1=1.f,aR2=1.f,aC1=0.f,aC2=0.f,aSl=0.f,aOf=0.f;
    float wyA[NBC];
    #pragma unroll
    for (int j = 0; j < NBC; j++) wyA[j] = 0.f;
    if (l < NACL){
        ac_coef(P_acltr[l], P_acltd[l], aA,aB,aR1,aR2,aC1,aC2);
        aSl = expf(P_aclsl[l]); aOf = P_aclof[l];
        #pragma unroll
        for (int j = 0; j < NBC; j++) wyA[j] = expf(P_lbcacl[l*NBC+j]);
    }

    // ---- ACG roles (pathway 2 only): g0 = lane (0..31), g1 = lane+32 (lanes 0..2) ----
    float gA=0.f,gB=0.f,gR1=1.f,gR2=1.f,gC1=0.f,gC2=0.f,gSl=0.f,gOf=0.f;
    float hA=0.f,hB=0.f,hR1=1.f,hR2=1.f,hC1=0.f,hC2=0.f,hSl=0.f,hOf=0.f;
    float wGa[NACL], wHa[NACL], wyG[NBC], wyH[NBC];
    #pragma unroll
    for (int j = 0; j < NACL; j++){ wGa[j]=0.f; wHa[j]=0.f; }
    #pragma unroll
    for (int j = 0; j < NBC; j++){ wyG[j]=0.f; wyH[j]=0.f; }
    if (path){
        ac_coef(P_acgtr[l], P_acgtd[l], gA,gB,gR1,gR2,gC1,gC2);
        gSl = expf(P_acgsl[l]); gOf = P_acgof[l];
        #pragma unroll
        for (int j = 0; j < NACL; j++) wGa[j] = -expf(P_laclacg[l*NACL+j]);
        #pragma unroll
        for (int j = 0; j < NBC; j++)  wyG[j] = expf(P_lbcacg[l*NBC+j]);
        if (l < 3){
            int h = l + 32;
            ac_coef(P_acgtr[h], P_acgtd[h], hA,hB,hR1,hR2,hC1,hC2);
            hSl = expf(P_acgsl[h]); hOf = P_acgof[h];
            #pragma unroll
            for (int j = 0; j < NACL; j++) wHa[j] = -expf(P_laclacg[h*NACL+j]);
            #pragma unroll
            for (int j = 0; j < NBC; j++)  wyH[j] = expf(P_lbcacg[h*NBC+j]);
        }
    }
    __syncwarp();

    float* relrow = g_rel + (path*NBC + ((l < NBC) ? l : 0))*RELSTRIDE;
    float E1a=0.f,E2a=0.f,E1g=0.f,E2g=0.f,E1h=0.f,E2h=0.f;
    int ri = 0;

    float fd0,fd1,fd2,fd3,fd4,fd5,fd6;
#define LOADCHUNK(k) do{ const float* _p = g_drive + (k)*224 + l; \
        fd0=_p[0]; fd1=_p[32]; fd2=_p[64]; fd3=_p[96]; fd4=_p[128]; fd5=_p[160]; fd6=_p[192]; }while(0)
#define STORECHUNK(bi) do{ float* _q = dbuf[bi] + l; \
        _q[0]=fd0; _q[32]=fd1; _q[64]=fd2; _q[96]=fd3; _q[128]=fd4; _q[160]=fd5; _q[192]=fd6; }while(0)

    LOADCHUNK(0); STORECHUNK(0); LOADCHUNK(1);
    __syncwarp();

    if (path == 0){
        // ---------- LNR pathway: ACL feedback only ----------
        for (int c = 0; c < NCHUNK; c++){
            int cur = c & 1;
            STORECHUNK(cur^1);
            int nk = (c+2 < NCHUNK) ? (c+2) : (NCHUNK-1);
            LOADCHUNK(nk);
            __syncwarp();
            const float* db = dbuf[cur];
            int tbase = c*16;
            #pragma unroll 4
            for (int i = 0; i < 16; i++){
                float xi = 0.f;
                if (l < NBC) xi = db[i*NBC + l];
                float cvA  = fmaf(aA, E1a, -aB*E2a);
                float aclo = fsig(aSl*(cvA - aOf));
                float fb0 = xi - c_off, fb1 = 0.f;
                #pragma unroll
                for (int j = 0; j < NACL; j++){
                    float v = __shfl_sync(0xffffffffu, aclo, j);
                    if (j & 1) fb1 = fmaf(wfbA[j], v, fb1);
                    else       fb0 = fmaf(wfbA[j], v, fb0);
                }
                float p = fsig(c_slope*(fb0+fb1));
                float relv = p*rrp;
                float t12 = c_p12*ip*(1.0f - rrp*c_irrp);
                ip  = ip + c_p01*(c_ipcap - ip) - t12;
                rrp = rrp + t12 - relv;
                if (l < NBC) relrow[tbase+i] = relv;
                float y0 = 0.f, y1 = 0.f;
                #pragma unroll
                for (int j = 0; j < NBC; j++){
                    float v = __shfl_sync(0xffffffffu, relv, j);
                    if (j & 1) y1 = fmaf(wyA[j], v, y1);
                    else       y0 = fmaf(wyA[j], v, y0);
                }
                float yA = y0 + y1;
                if (l < NACL){
                    float yo = ringA[l*53+ri];
                    ringA[l*53+ri] = yA;
                    E1a = fmaf(aR1, E1a, fmaf(-aC1, yo, yA));
                    E2a = fmaf(aR2, E2a, fmaf(-aC2, yo, yA));
                }
                ri = (ri == KACN-1) ? 0 : ri+1;
            }
            __syncwarp();
        }
    } else {
        // ---------- BCN pathway: ACL + ACG feedback ----------
        for (int c = 0; c < NCHUNK; c++){
            int cur = c & 1;
            STORECHUNK(cur^1);
            int nk = (c+2 < NCHUNK) ? (c+2) : (NCHUNK-1);
            LOADCHUNK(nk);
            __syncwarp();
            const float* db = dbuf[cur];
            int tbase = c*16;
            #pragma unroll 2
            for (int i = 0; i < 16; i++){
                float xi = 0.f;
                if (l < NBC) xi = db[i*NBC + l];
                float cvA  = fmaf(aA, E1a, -aB*E2a);
                float aclo = fsig(aSl*(cvA - aOf));
                float preG = fmaf(gA, E1g, -gB*E2g) - gOf;
                float preH = fmaf(hA, E1h, -hB*E2h) - hOf;
                float fbv[4];
                fbv[0] = xi - c_off; fbv[1] = 0.f; fbv[2] = 0.f; fbv[3] = 0.f;
                #pragma unroll
                for (int j = 0; j < NACL; j++){
                    float v = __shfl_sync(0xffffffffu, aclo, j);
                    preG = fmaf(wGa[j], v, preG);
                    preH = fmaf(wHa[j], v, preH);
                    fbv[j & 3] = fmaf(wfbA[j], v, fbv[j & 3]);
                }
                float acgo = fsig(gSl*preG);
                float acgh = fsig(hSl*preH);
                #pragma unroll
                for (int j = 0; j < 32; j++){
                    float v = __shfl_sync(0xffffffffu, acgo, j);
                    fbv[j & 3] = fmaf(wfbG[j], v, fbv[j & 3]);
                }
                #pragma unroll
                for (int j = 0; j < 3; j++){
                    float v = __shfl_sync(0xffffffffu, acgh, j);
                    fbv[j] = fmaf(wfbG[32+j], v, fbv[j]);
                }
                float p = fsig(c_slope*((fbv[0]+fbv[1])+(fbv[2]+fbv[3])));
                float relv = p*rrp;
                float t12 = c_p12*ip*(1.0f - rrp*c_irrp);
                ip  = ip + c_p01*(c_ipcap - ip) - t12;
                rrp = rrp + t12 - relv;
                if (l < NBC) relrow[tbase+i] = relv;
                float ya0=0.f,ya1=0.f,yg0=0.f,yg1=0.f,yh0=0.f,yh1=0.f;
                #pragma unroll
                for (int j = 0; j < NBC; j++){
                    float v = __shfl_sync(0xffffffffu, relv, j);
                    if (j & 1){
                        ya1 = fmaf(wyA[j], v, ya1);
                        yg1 = fmaf(wyG[j], v, yg1);
                        yh1 = fmaf(wyH[j], v, yh1);
                    } else {
                        ya0 = fmaf(wyA[j], v, ya0);
                        yg0 = fmaf(wyG[j], v, yg0);
                        yh0 = fmaf(wyH[j], v, yh0);
                    }
                }
                float yA = ya0+ya1, yG = yg0+yg1, yH = yh0+yh1;
                if (l < NACL){
                    float yo = ringA[l*53+ri];
                    ringA[l*53+ri] = yA;
                    E1a = fmaf(aR1, E1a, fmaf(-aC1, yo, yA));
                    E2a = fmaf(aR2, E2a, fmaf(-aC2, yo, yA));
                }
                {
                    float yo = ringG[l*53+ri];
                    ringG[l*53+ri] = yG;
                    E1g = fmaf(gR1, E1g, fmaf(-gC1, yo, yG));
                    E2g = fmaf(gR2, E2g, fmaf(-gC2, yo, yG));
                }
                if (l < 3){
                    float yo = ringG[(l+32)*53+ri];
                    ringG[(l+32)*53+ri] = yH;
                    E1h = fmaf(hR1, E1h, fmaf(-hC1, yo, yH));
                    E2h = fmaf(hR2, E2h, fmaf(-hC2, yo, yH));
                }
                ri = (ri == KACN-1) ? 0 : ri+1;
            }
            __syncwarp();
        }
    }
#undef LOADCHUNK
#undef STORECHUNK
}

// ---------------- iGluSnFR readout: 32-tap FIR over rel ----------------
__global__ void out_kernel(float* __restrict__ out){
    __shared__ float skg[K1];
    int tid = threadIdx.x;
    if (tid < K1) skg[tid] = g_kglu[tid];
    __syncthreads();
    int oid = blockIdx.x*blockDim.x + tid;
    if (oid >= 2*NBC*TN) return;
    int n  = oid & (TN-1);
    int pc = oid >> 15;
    const float* r = g_rel + pc*RELSTRIDE + n;
    float a0 = 0.f, a1 = 0.f;
    #pragma unroll
    for (int j = 0; j < K1; j++){
        float v = r[K1-1-j];                 /* rel[n+31-j] */
        if (j & 1) a1 = fmaf(skg[j], v, a1);
        else       a0 = fmaf(skg[j], v, a0);
    }
    out[oid] = a0 + a1;
}

extern "C" void kernel_launch(void* const* d_in, const int* in_sizes, int n_in,
                              void* d_out, int out_size){
    (void)in_sizes; (void)n_in; (void)out_size;
    const float* x  = (const float*)d_in[0];
    const float* sb = (const float*)d_in[1];
    const float* ss = (const float*)d_in[2];

    setup_kernel<<<1, 64>>>((const float*)d_in[3]);
    xp_kernel<<<(XPLEN+255)/256, 256>>>(x, sb, ss);
    drive_kernel<<<(NSTEPS+127)/128, 128>>>();
    scan_kernel<<<2, 32>>>(
        (const float*)d_in[4],  (const float*)d_in[5],
        (const float*)d_in[6],  (const float*)d_in[7],
        (const float*)d_in[8],  (const float*)d_in[9],
        (const float*)d_in[10], (const float*)d_in[11],
        (const float*)d_in[12], (const float*)d_in[13],
        (const float*)d_in[14], (const float*)d_in[15],
        (const float*)d_in[16], (const float*)d_in[17],
        (const float*)d_in[18], (const float*)d_in[19],
        (const float*)d_in[20], (const float*)d_in[21],
        (const float*)d_in[22], (const float*)d_in[23],
        (const float*)d_in[24], (const float*)d_in[25]);
    out_kernel<<<(2*NBC*TN+255)/256, 256>>>((float*)d_out);
}